// round 11
// baseline (speedup 1.0000x reference)
#include <cuda_runtime.h>
#include <cstdint>
#include <math.h>

// Problem constants: B=16384, A=50, D=256, alpha=0.2
constexpr int Bn = 16384;
constexpr int An = 50;
constexpr int Dn = 256;
constexpr float ALPHA = 0.2f;

constexpr int NTHREADS = 256;              // 8 warps
constexpr int D4 = Dn / 4;                 // 64
constexpr int ROWS_T = An + 1;             // 51 rows: 50 attrs + entity row
constexpr int TILE_FLOATS = ROWS_T * Dn;   // 13056
constexpr int ATTR_BYTES = An * Dn * 4;    // 51200 (contiguous per b)
constexpr int ENT_BYTES  = Dn * 4;         // 1024
// dynamic smem: 2 tiles + e_s[64] + att_s[64] + 2 mbars
constexpr int SMEM_FLOATS = 2 * TILE_FLOATS + 64 + 64 + 8;
constexpr int SMEM_BYTES  = SMEM_FLOATS * (int)sizeof(float);   // ~102.6 KB

__device__ __forceinline__ uint32_t smem_u32(const void* p) {
    uint32_t a;
    asm("{ .reg .u64 t; cvta.to.shared.u64 t, %1; cvt.u32.u64 %0, t; }"
        : "=r"(a) : "l"(p));
    return a;
}

__device__ __forceinline__ void mbar_wait0(uint32_t mbar_a) {
    uint32_t done;
    asm volatile("{\n\t.reg .pred p;\n\t"
                 "mbarrier.try_wait.parity.acquire.cta.shared::cta.b64 p, [%1], 0;\n\t"
                 "selp.b32 %0, 1, 0, p;\n\t}"
                 : "=r"(done) : "r"(mbar_a) : "memory");
    if (!done) {
        asm volatile("{\n\t.reg .pred P1;\n\t"
                     "WL_%=:\n\t"
                     "mbarrier.try_wait.parity.acquire.cta.shared::cta.b64 P1, [%0], 0, 0x989680;\n\t"
                     "@P1 bra.uni WD_%=;\n\t"
                     "bra.uni WL_%=;\n\t"
                     "WD_%=:\n\t}"
                     :: "r"(mbar_a) : "memory");
    }
}

__device__ __forceinline__ float dot8(const float4& x0, const float4& x1,
                                      const float4& y0, const float4& y1) {
    return x0.x*y0.x + x0.y*y0.y + x0.z*y0.z + x0.w*y0.w
         + x1.x*y1.x + x1.y*y1.y + x1.z*y1.z + x1.w*y1.w;
}

// Compute one batch element from its SMEM tile (51 rows x 256 fp32).
__device__ __forceinline__ void process_tile(
    const float4* __restrict__ tile4, float* e_s, float* att_s,
    const float4 aa0, const float4 aa1, const float4* __restrict__ a4,
    float* __restrict__ out, size_t b, int t, int w, int lane)
{
    // ---- Pass 1: scores from SMEM (conflict-free LDS.128) ---------------
    // Warp w owns rows a = w + 8k; k=0..5 always valid, k=6: a=48+w for w<3
    // (w==2 -> row 50 = entity row, dotted against a_ent).
    float p[7];
#pragma unroll
    for (int k = 0; k < 6; k++) {
        const int a = w + 8 * k;
        const float4 v0 = tile4[a * D4 + lane];
        const float4 v1 = tile4[a * D4 + 32 + lane];
        p[k] = dot8(v0, v1, aa0, aa1);
    }
    p[6] = 0.f;
    if (w < 3) {
        const int a = 48 + w;                    // 48, 49, 50(entity)
        const float4 v0 = tile4[a * D4 + lane];
        const float4 v1 = tile4[a * D4 + 32 + lane];
        if (w == 2) {
            const float4 ce0 = __ldg(a4 + 64 + lane);
            const float4 ce1 = __ldg(a4 + 96 + lane);
            p[6] = dot8(v0, v1, ce0, ce1);
        } else {
            p[6] = dot8(v0, v1, aa0, aa1);
        }
    }

    // Batched warp reductions: 7 independent values, 5 rounds
#pragma unroll
    for (int off = 16; off; off >>= 1) {
#pragma unroll
        for (int k = 0; k < 7; k++)
            p[k] += __shfl_xor_sync(0xffffffffu, p[k], off);
    }
    if (lane == 0) {
#pragma unroll
        for (int k = 0; k < 6; k++)
            e_s[w + 8 * k] = p[k];
        if (w < 3) e_s[48 + w] = p[6];           // slot 50 = entity bias
    }
    __syncthreads();

    // ---- Softmax over 50 scores (single warp) ---------------------------
    if (w == 0) {
        const float bias = e_s[An];
        float e0 = (lane      < An) ? e_s[lane]      + bias : -INFINITY;
        float e1 = (lane + 32 < An) ? e_s[lane + 32] + bias : -INFINITY;
        e0 = (e0 > 0.f) ? e0 : ALPHA * e0;       // leaky_relu; -inf stays -inf
        e1 = (e1 > 0.f) ? e1 : ALPHA * e1;

        float m = fmaxf(e0, e1);
#pragma unroll
        for (int off = 16; off; off >>= 1)
            m = fmaxf(m, __shfl_xor_sync(0xffffffffu, m, off));
        float q0 = __expf(e0 - m);               // exp(-inf)=0 for masked lanes
        float q1 = __expf(e1 - m);
        float s = q0 + q1;
#pragma unroll
        for (int off = 16; off; off >>= 1)
            s += __shfl_xor_sync(0xffffffffu, s, off);

        const float scale = (float)An / s;       // softmax * attr_num
        if (lane      < An) att_s[lane]      = q0 * scale;
        if (lane + 32 < An) att_s[lane + 32] = q1 * scale;
    }
    __syncthreads();

    // ---- Pass 2: out[b, d] = sum_a att[a] * tile[a, d] -------------------
    if (t < D4) {
        float4 acc = make_float4(0.f, 0.f, 0.f, 0.f);
#pragma unroll
        for (int a = 0; a < An; a++) {
            const float att = att_s[a];
            const float4 v  = tile4[a * D4 + t];
            acc.x = fmaf(att, v.x, acc.x);
            acc.y = fmaf(att, v.y, acc.y);
            acc.z = fmaf(att, v.z, acc.z);
            acc.w = fmaf(att, v.w, acc.w);
        }
        reinterpret_cast<float4*>(out)[b * D4 + t] = acc;
    }
}

__global__ __launch_bounds__(NTHREADS, 2)
void struct_attention_kernel(const float* __restrict__ attrs,   // [B, A, D]
                             const float* __restrict__ ent,     // [B, D]
                             const float* __restrict__ avec,    // [2D, 1]
                             float* __restrict__ out)           // [B, D]
{
    extern __shared__ float smem[];
    float*  tile0 = smem;                        // 51 rows x 256
    float*  tile1 = smem + TILE_FLOATS;
    float*  e_s   = smem + 2 * TILE_FLOATS;      // 64 slots (uses 51)
    float*  att_s = e_s + 64;                    // 64 slots (uses 50)
    unsigned long long* mbar = reinterpret_cast<unsigned long long*>(att_s + 64);

    const size_t b0 = 2 * (size_t)blockIdx.x;
    const size_t b1 = b0 + 1;
    const int t    = threadIdx.x;
    const int w    = t >> 5;                     // 0..7, warp-uniform
    const int lane = t & 31;

    const uint32_t mbar0_a = smem_u32(&mbar[0]);
    const uint32_t mbar1_a = smem_u32(&mbar[1]);
    const uint32_t tile0_a = smem_u32(tile0);
    const uint32_t tile1_a = smem_u32(tile1);

    // ---- Init barriers, then issue BOTH tiles' TMA loads up-front --------
    if (t == 0) {
        asm volatile("mbarrier.init.shared.b64 [%0], 1;" :: "r"(mbar0_a) : "memory");
        asm volatile("mbarrier.init.shared.b64 [%0], 1;" :: "r"(mbar1_a) : "memory");
    }
    __syncthreads();
    if (t == 0) {
        // buffer 0 <- b0
        asm volatile("mbarrier.arrive.expect_tx.shared.b64 _, [%0], %1;"
                     :: "r"(mbar0_a), "r"((uint32_t)(ATTR_BYTES + ENT_BYTES)) : "memory");
        const float* sA0 = attrs + b0 * (An * Dn);
        const float* sE0 = ent   + b0 * Dn;
        asm volatile("cp.async.bulk.shared::cta.global.mbarrier::complete_tx::bytes "
                     "[%0], [%1], %2, [%3];"
                     :: "r"(tile0_a), "l"(sA0), "r"((uint32_t)ATTR_BYTES), "r"(mbar0_a) : "memory");
        asm volatile("cp.async.bulk.shared::cta.global.mbarrier::complete_tx::bytes "
                     "[%0], [%1], %2, [%3];"
                     :: "r"(tile0_a + ATTR_BYTES), "l"(sE0), "r"((uint32_t)ENT_BYTES), "r"(mbar0_a) : "memory");
        // buffer 1 <- b1 (streams while we compute b0)
        asm volatile("mbarrier.arrive.expect_tx.shared.b64 _, [%0], %1;"
                     :: "r"(mbar1_a), "r"((uint32_t)(ATTR_BYTES + ENT_BYTES)) : "memory");
        const float* sA1 = attrs + b1 * (An * Dn);
        const float* sE1 = ent   + b1 * Dn;
        asm volatile("cp.async.bulk.shared::cta.global.mbarrier::complete_tx::bytes "
                     "[%0], [%1], %2, [%3];"
                     :: "r"(tile1_a), "l"(sA1), "r"((uint32_t)ATTR_BYTES), "r"(mbar1_a) : "memory");
        asm volatile("cp.async.bulk.shared::cta.global.mbarrier::complete_tx::bytes "
                     "[%0], [%1], %2, [%3];"
                     :: "r"(tile1_a + ATTR_BYTES), "l"(sE1), "r"((uint32_t)ENT_BYTES), "r"(mbar1_a) : "memory");
    }

    const float4* a4  = reinterpret_cast<const float4*>(avec);   // [0,64)=a_attr, [64,128)=a_ent
    const float4 aa0 = __ldg(a4 + lane);
    const float4 aa1 = __ldg(a4 + 32 + lane);

    // ---- b0: wait buffer 0, compute --------------------------------------
    mbar_wait0(mbar0_a);
    process_tile(reinterpret_cast<const float4*>(tile0), e_s, att_s,
                 aa0, aa1, a4, out, b0, t, w, lane);

    // ---- b1: wait buffer 1 (likely already done), compute ----------------
    mbar_wait0(mbar1_a);
    process_tile(reinterpret_cast<const float4*>(tile1), e_s, att_s,
                 aa0, aa1, a4, out, b1, t, w, lane);
}

extern "C" void kernel_launch(void* const* d_in, const int* in_sizes, int n_in,
                              void* d_out, int out_size)
{
    const float* attrs = (const float*)d_in[0];   // [B, A, D] fp32
    const float* ent   = (const float*)d_in[1];   // [B, D]    fp32
    const float* avec  = (const float*)d_in[2];   // [2D, 1]   fp32
    float* out         = (float*)d_out;           // [B, D]    fp32

    cudaFuncSetAttribute(struct_attention_kernel,
                         cudaFuncAttributeMaxDynamicSharedMemorySize, SMEM_BYTES);

    struct_attention_kernel<<<Bn / 2, NTHREADS, SMEM_BYTES>>>(attrs, ent, avec, out);
}

// round 16
// speedup vs baseline: 1.0414x; 1.0414x over previous
#include <cuda_runtime.h>
#include <cstdint>
#include <math.h>

// Problem constants: B=16384, A=50, D=256, alpha=0.2
constexpr int Bn = 16384;
constexpr int An = 50;
constexpr int Dn = 256;
constexpr float ALPHA = 0.2f;

constexpr int NTHREADS = 256;              // 8 warps
constexpr int D4 = Dn / 4;                 // 64
constexpr int ROWS_T = An + 1;             // 51 rows: 50 attrs + entity row
constexpr int TILE_FLOATS = ROWS_T * Dn;   // 13056
constexpr int ATTR_BYTES = An * Dn * 4;    // 51200 (contiguous per b)
constexpr int ENT_BYTES  = Dn * 4;         // 1024
// chunk split: rows 0..23 (k=0..2 of every warp) | rows 24..49 + entity (k=3..6)
constexpr int CH0_BYTES = 24 * Dn * 4;     // 24576
constexpr int CH1_BYTES = ATTR_BYTES - CH0_BYTES;   // 26624 (rows 24..49)
// dynamic smem: tile + e_s[64] + att_s[64] + 2 mbars
constexpr int SMEM_FLOATS = TILE_FLOATS + 64 + 64 + 8;
constexpr int SMEM_BYTES  = SMEM_FLOATS * (int)sizeof(float);   // ~52.8 KB

__device__ __forceinline__ uint32_t smem_u32(const void* p) {
    uint32_t a;
    asm("{ .reg .u64 t; cvta.to.shared.u64 t, %1; cvt.u32.u64 %0, t; }"
        : "=r"(a) : "l"(p));
    return a;
}

__device__ __forceinline__ void mbar_wait0(uint32_t mbar_a) {
    uint32_t done;
    asm volatile("{\n\t.reg .pred p;\n\t"
                 "mbarrier.try_wait.parity.acquire.cta.shared::cta.b64 p, [%1], 0;\n\t"
                 "selp.b32 %0, 1, 0, p;\n\t}"
                 : "=r"(done) : "r"(mbar_a) : "memory");
    if (!done) {
        asm volatile("{\n\t.reg .pred P1;\n\t"
                     "WL_%=:\n\t"
                     "mbarrier.try_wait.parity.acquire.cta.shared::cta.b64 P1, [%0], 0, 0x989680;\n\t"
                     "@P1 bra.uni WD_%=;\n\t"
                     "bra.uni WL_%=;\n\t"
                     "WD_%=:\n\t}"
                     :: "r"(mbar_a) : "memory");
    }
}

__device__ __forceinline__ float dot8(const float4& x0, const float4& x1,
                                      const float4& y0, const float4& y1) {
    return x0.x*y0.x + x0.y*y0.y + x0.z*y0.z + x0.w*y0.w
         + x1.x*y1.x + x1.y*y1.y + x1.z*y1.z + x1.w*y1.w;
}

__global__ __launch_bounds__(NTHREADS, 4)
void struct_attention_kernel(const float* __restrict__ attrs,   // [B, A, D]
                             const float* __restrict__ ent,     // [B, D]
                             const float* __restrict__ avec,    // [2D, 1]
                             float* __restrict__ out)           // [B, D]
{
    extern __shared__ float smem[];
    float*  tile  = smem;                        // 51 rows x 256
    float*  e_s   = smem + TILE_FLOATS;          // 64 slots (uses 51)
    float*  att_s = e_s + 64;                    // 64 slots (uses 50)
    unsigned long long* mbar = reinterpret_cast<unsigned long long*>(att_s + 64);
    float4* tile4 = reinterpret_cast<float4*>(tile);

    const size_t b  = blockIdx.x;
    const int t     = threadIdx.x;
    const int w     = t >> 5;                    // 0..7, warp-uniform
    const int lane  = t & 31;

    const uint32_t mbar0_a = smem_u32(&mbar[0]);
    const uint32_t mbar1_a = smem_u32(&mbar[1]);
    const uint32_t tile_a  = smem_u32(tile);

    // ---- Init barriers, issue BOTH chunk loads up-front ------------------
    if (t == 0) {
        asm volatile("mbarrier.init.shared.b64 [%0], 1;" :: "r"(mbar0_a) : "memory");
        asm volatile("mbarrier.init.shared.b64 [%0], 1;" :: "r"(mbar1_a) : "memory");
    }
    __syncthreads();
    if (t == 0) {
        const float* srcA = attrs + b * (An * Dn);
        const float* srcE = ent   + b * Dn;
        // chunk0: rows 0..23
        asm volatile("mbarrier.arrive.expect_tx.shared.b64 _, [%0], %1;"
                     :: "r"(mbar0_a), "r"((uint32_t)CH0_BYTES) : "memory");
        asm volatile("cp.async.bulk.shared::cta.global.mbarrier::complete_tx::bytes "
                     "[%0], [%1], %2, [%3];"
                     :: "r"(tile_a), "l"(srcA), "r"((uint32_t)CH0_BYTES), "r"(mbar0_a) : "memory");
        // chunk1: rows 24..49 + entity row (slot 50)
        asm volatile("mbarrier.arrive.expect_tx.shared.b64 _, [%0], %1;"
                     :: "r"(mbar1_a), "r"((uint32_t)(CH1_BYTES + ENT_BYTES)) : "memory");
        asm volatile("cp.async.bulk.shared::cta.global.mbarrier::complete_tx::bytes "
                     "[%0], [%1], %2, [%3];"
                     :: "r"(tile_a + CH0_BYTES),
                        "l"(reinterpret_cast<const char*>(srcA) + CH0_BYTES),
                        "r"((uint32_t)CH1_BYTES), "r"(mbar1_a) : "memory");
        asm volatile("cp.async.bulk.shared::cta.global.mbarrier::complete_tx::bytes "
                     "[%0], [%1], %2, [%3];"
                     :: "r"(tile_a + ATTR_BYTES), "l"(srcE),
                        "r"((uint32_t)ENT_BYTES), "r"(mbar1_a) : "memory");
    }

    const float4* a4  = reinterpret_cast<const float4*>(avec);   // [0,64)=a_attr, [64,128)=a_ent
    const float4 aa0 = __ldg(a4 + lane);
    const float4 aa1 = __ldg(a4 + 32 + lane);

    // ---- Pass 1a: chunk0 partials (rows k=0..2) overlap chunk1 stream ----
    float p[7];
    mbar_wait0(mbar0_a);
#pragma unroll
    for (int k = 0; k < 3; k++) {
        const int a = w + 8 * k;                 // 0..23
        const float4 v0 = tile4[a * D4 + lane];
        const float4 v1 = tile4[a * D4 + 32 + lane];
        p[k] = dot8(v0, v1, aa0, aa1);
    }

    // ---- Pass 1b: chunk1 partials (rows k=3..6) --------------------------
    mbar_wait0(mbar1_a);
#pragma unroll
    for (int k = 3; k < 6; k++) {
        const int a = w + 8 * k;                 // 24..47
        const float4 v0 = tile4[a * D4 + lane];
        const float4 v1 = tile4[a * D4 + 32 + lane];
        p[k] = dot8(v0, v1, aa0, aa1);
    }
    p[6] = 0.f;
    if (w < 3) {
        const int a = 48 + w;                    // 48, 49, 50(entity)
        const float4 v0 = tile4[a * D4 + lane];
        const float4 v1 = tile4[a * D4 + 32 + lane];
        if (w == 2) {
            const float4 ce0 = __ldg(a4 + 64 + lane);
            const float4 ce1 = __ldg(a4 + 96 + lane);
            p[6] = dot8(v0, v1, ce0, ce1);
        } else {
            p[6] = dot8(v0, v1, aa0, aa1);
        }
    }

    // Batched warp reductions: 7 independent values, 5 rounds
#pragma unroll
    for (int off = 16; off; off >>= 1) {
#pragma unroll
        for (int k = 0; k < 7; k++)
            p[k] += __shfl_xor_sync(0xffffffffu, p[k], off);
    }
    if (lane == 0) {
#pragma unroll
        for (int k = 0; k < 6; k++)
            e_s[w + 8 * k] = p[k];
        if (w < 3) e_s[48 + w] = p[6];           // slot 50 = entity bias
    }
    __syncthreads();

    // ---- Softmax over 50 scores (single warp) ----------------------------
    if (w == 0) {
        const float bias = e_s[An];
        float e0 = (lane      < An) ? e_s[lane]      + bias : -INFINITY;
        float e1 = (lane + 32 < An) ? e_s[lane + 32] + bias : -INFINITY;
        e0 = (e0 > 0.f) ? e0 : ALPHA * e0;       // leaky_relu; -inf stays -inf
        e1 = (e1 > 0.f) ? e1 : ALPHA * e1;

        float m = fmaxf(e0, e1);
#pragma unroll
        for (int off = 16; off; off >>= 1)
            m = fmaxf(m, __shfl_xor_sync(0xffffffffu, m, off));
        float q0 = __expf(e0 - m);               // exp(-inf)=0 for masked lanes
        float q1 = __expf(e1 - m);
        float s = q0 + q1;
#pragma unroll
        for (int off = 16; off; off >>= 1)
            s += __shfl_xor_sync(0xffffffffu, s, off);

        const float scale = (float)An / s;       // softmax * attr_num
        if (lane      < An) att_s[lane]      = q0 * scale;
        if (lane + 32 < An) att_s[lane + 32] = q1 * scale;
    }
    __syncthreads();

    // ---- Pass 2: out[b, d] = sum_a att[a] * tile[a, d] -------------------
    if (t < D4) {
        float4 acc = make_float4(0.f, 0.f, 0.f, 0.f);
#pragma unroll
        for (int a = 0; a < An; a++) {
            const float att = att_s[a];
            const float4 v  = tile4[a * D4 + t];
            acc.x = fmaf(att, v.x, acc.x);
            acc.y = fmaf(att, v.y, acc.y);
            acc.z = fmaf(att, v.z, acc.z);
            acc.w = fmaf(att, v.w, acc.w);
        }
        reinterpret_cast<float4*>(out)[b * D4 + t] = acc;
    }
}

extern "C" void kernel_launch(void* const* d_in, const int* in_sizes, int n_in,
                              void* d_out, int out_size)
{
    const float* attrs = (const float*)d_in[0];   // [B, A, D] fp32
    const float* ent   = (const float*)d_in[1];   // [B, D]    fp32
    const float* avec  = (const float*)d_in[2];   // [2D, 1]   fp32
    float* out         = (float*)d_out;           // [B, D]    fp32

    cudaFuncSetAttribute(struct_attention_kernel,
                         cudaFuncAttributeMaxDynamicSharedMemorySize, SMEM_BYTES);

    struct_attention_kernel<<<Bn, NTHREADS, SMEM_BYTES>>>(attrs, ent, avec, out);
}